// round 16
// baseline (speedup 1.0000x reference)
#include <cuda_runtime.h>
#include <cuda_bf16.h>
#include <cstdint>

#define SEQ      4096
#define DIM      768
#define NH       12
#define HD       64
#define QKVDIM   2304
#define WIN      64      // WINDOW/2

// ---------------- scratch (device globals; no allocation allowed) -----------
__device__ __nv_bfloat16 g_xh[SEQ * DIM],    g_xl[SEQ * DIM];
__device__ __nv_bfloat16 g_wqh[QKVDIM * DIM], g_wql[QKVDIM * DIM];
__device__ __nv_bfloat16 g_woh[DIM * DIM],   g_wol[DIM * DIM];
__device__ __nv_bfloat16 g_qh[NH * SEQ * HD], g_ql[NH * SEQ * HD];
__device__ __nv_bfloat16 g_kh[NH * SEQ * HD], g_kl[NH * SEQ * HD];
__device__ __nv_bfloat16 g_vh[NH * SEQ * HD], g_vl[NH * SEQ * HD];
__device__ __nv_bfloat16 g_aoh[SEQ * DIM],   g_aol[SEQ * DIM];
__device__ float g_cos[SEQ * 32], g_sin[SEQ * 32];   // RoPE tables

// =================== common helpers ==========================================
__device__ __forceinline__ uint32_t smem_u32(const void* p) {
    uint32_t a;
    asm("{ .reg .u64 t; cvta.to.shared.u64 t, %1; cvt.u32.u64 %0, t; }" : "=r"(a) : "l"(p));
    return a;
}
#define LDSM4(r, addr) \
    asm volatile("ldmatrix.sync.aligned.m8n8.x4.shared.b16 {%0,%1,%2,%3}, [%4];" \
        : "=r"((r)[0]), "=r"((r)[1]), "=r"((r)[2]), "=r"((r)[3]) : "r"(addr))
#define LDSM4T(r, addr) \
    asm volatile("ldmatrix.sync.aligned.m8n8.x4.trans.shared.b16 {%0,%1,%2,%3}, [%4];" \
        : "=r"((r)[0]), "=r"((r)[1]), "=r"((r)[2]), "=r"((r)[3]) : "r"(addr))
#define MMA_BF16(d, a, b0, b1) \
    asm volatile("mma.sync.aligned.m16n8k16.row.col.f32.bf16.bf16.f32 " \
        "{%0,%1,%2,%3}, {%4,%5,%6,%7}, {%8,%9}, {%0,%1,%2,%3};" \
        : "+f"((d)[0]), "+f"((d)[1]), "+f"((d)[2]), "+f"((d)[3]) \
        : "r"((a)[0]), "r"((a)[1]), "r"((a)[2]), "r"((a)[3]), "r"(b0), "r"(b1))
#define CP16(dst, src) \
    asm volatile("cp.async.cg.shared.global [%0], [%1], 16;" :: "r"(dst), "l"(src))
#define CP_COMMIT() asm volatile("cp.async.commit_group;" ::: "memory")
template<int N>
__device__ __forceinline__ void cp_wait() {
    asm volatile("cp.async.wait_group %0;" :: "n"(N) : "memory");
}

__device__ __forceinline__ uint32_t pack_bf2(__nv_bfloat16 a, __nv_bfloat16 b) {
    __nv_bfloat162 t(a, b);
    return *reinterpret_cast<uint32_t*>(&t);
}
__device__ __forceinline__ void split2(float x, float y, uint32_t& hi, uint32_t& lo) {
    __nv_bfloat16 hx = __float2bfloat16(x);
    __nv_bfloat16 hy = __float2bfloat16(y);
    __nv_bfloat16 lx = __float2bfloat16(x - __bfloat162float(hx));
    __nv_bfloat16 ly = __float2bfloat16(y - __bfloat162float(hy));
    hi = pack_bf2(hx, hy);
    lo = pack_bf2(lx, ly);
}
// swizzled smem byte offset, 64B rows: (row r, 16B chunk c in 0..3)
__device__ __forceinline__ uint32_t swz64(int r, int c) {
    return (uint32_t)(r * 64 + ((c ^ ((r >> 1) & 3)) * 16));
}

// =================== fused preprocessing =====================================
#define NX  (SEQ * DIM / 4)
#define NWQ (QKVDIM * DIM / 4)
#define NWO (DIM * DIM / 4)
#define NRT (SEQ * 32)
#define NPRE (NX + NWQ + NWO + NRT)

__global__ void preproc_kernel(const float* __restrict__ x,
                               const float* __restrict__ wqkv,
                               const float* __restrict__ wo,
                               const int* __restrict__ posids)
{
    int g = blockIdx.x * blockDim.x + threadIdx.x;
    if (g >= NPRE) return;

    const float* src;
    __nv_bfloat16 *hi, *lo;
    int i;
    if (g < NX)                  { src = x;    hi = g_xh;  lo = g_xl;  i = g; }
    else if (g < NX + NWQ)       { src = wqkv; hi = g_wqh; lo = g_wql; i = g - NX; }
    else if (g < NX + NWQ + NWO) { src = wo;   hi = g_woh; lo = g_wol; i = g - NX - NWQ; }
    else {
        int idx = g - NX - NWQ - NWO;
        int ri = idx & 31, s = idx >> 5;
        float f = (float)posids[s] * powf(10000.f, -(float)ri / 32.f);
        g_cos[idx] = cosf(f);
        g_sin[idx] = sinf(f);
        return;
    }
    i *= 4;
    float4 v = *(const float4*)(src + i);
    uint2 h, l;
    split2(v.x, v.y, h.x, l.x);
    split2(v.z, v.w, h.y, l.y);
    *(uint2*)(hi + i) = h;
    *(uint2*)(lo + i) = l;
}

// =================== bf16 HMMA GEMM, 3-MMA compensation, cp.async ============
// BK=32, 256 threads, NSTG-stage cp.async pipeline, 2 CTAs/SM.
// B register fragments double-buffered: LDSM for p+1 issued before MMAs of p.
template<int BM, bool ROPE, int NSTG>
__global__ void __launch_bounds__(256, 2) gemm_bf16_kernel(
    const __nv_bfloat16* __restrict__ Ah, const __nv_bfloat16* __restrict__ Al,
    const __nv_bfloat16* __restrict__ Bh, const __nv_bfloat16* __restrict__ Bl,
    float* __restrict__ C, int M, int N, int K)
{
    constexpr int NT  = (BM == 128) ? 8 : 4;
    constexpr int NP  = NT / 2;
    constexpr int TA  = BM * 64;
    constexpr int TB  = 128 * 64;
    constexpr int STG = 2 * (TA + TB);

    extern __shared__ char smem[];
    const uint32_t sb0 = smem_u32(smem);

    const int tid  = threadIdx.x;
    const int wid  = tid >> 5;
    const int lane = tid & 31;
    const int m0 = blockIdx.y * BM;
    const int n0 = blockIdx.x * 128;
    const int wm = (BM == 128) ? (wid & 3) * 32 : (wid & 1) * 32;
    const int wn = (BM == 128) ? (wid >> 2) * 64 : (wid >> 1) * 32;

    const __nv_bfloat16* Ahb = Ah + (size_t)m0 * K;
    const __nv_bfloat16* Alb = Al + (size_t)m0 * K;
    const __nv_bfloat16* Bhb = Bh + (size_t)n0 * K;
    const __nv_bfloat16* Blb = Bl + (size_t)n0 * K;

    auto cp_stage = [&](int c, int s) {
        const int kc = c * 32;
        const uint32_t base = sb0 + s * STG;
#pragma unroll
        for (int i = 0; i < BM * 4 / 256; i++) {
            int f = tid + i * 256;
            int r = f >> 2, sg = f & 3;
            uint32_t off = swz64(r, sg);
            const size_t go = (size_t)r * K + kc + sg * 8;
            CP16(base + off,      Ahb + go);
            CP16(base + TA + off, Alb + go);
        }
#pragma unroll
        for (int i = 0; i < 2; i++) {
            int f = tid + i * 256;
            int r = f >> 2, sg = f & 3;
            uint32_t off = swz64(r, sg);
            const size_t go = (size_t)r * K + kc + sg * 8;
            CP16(base + 2 * TA + off,      Bhb + go);
            CP16(base + 2 * TA + TB + off, Blb + go);
        }
    };

    float acc[2][NT][4];
#pragma unroll
    for (int i = 0; i < 2; i++)
#pragma unroll
        for (int j = 0; j < NT; j++)
#pragma unroll
            for (int t = 0; t < 4; t++) acc[i][j][t] = 0.f;

    auto compute = [&](int s) {
        const uint32_t base = sb0 + s * STG;
        const uint32_t aHi = base, aLo = base + TA;
        const uint32_t bHi = base + 2 * TA, bLo = base + 2 * TA + TB;
        const int quad = lane >> 3, l8 = lane & 7;
#pragma unroll
        for (int ks = 0; ks < 2; ks++) {
            uint32_t Ahf[2][4], Alf[2][4];
#pragma unroll
            for (int mt = 0; mt < 2; mt++) {
                int r = wm + mt * 16 + (lane & 15);
                int ch = ks * 2 + (lane >> 4);
                uint32_t off = swz64(r, ch);
                LDSM4(Ahf[mt], aHi + off);
                LDSM4(Alf[mt], aLo + off);
            }
            // double-buffered B fragments: prefetch p+1 before MMAs of p
            uint32_t Bhf[2][4], Blf[2][4];
            auto loadB = [&](int p, int buf) {
                int n = wn + p * 16 + (quad >> 1) * 8 + l8;
                int ch = ks * 2 + (quad & 1);
                uint32_t off = swz64(n, ch);
                LDSM4(Bhf[buf], bHi + off);
                LDSM4(Blf[buf], bLo + off);
            };
            loadB(0, 0);
#pragma unroll
            for (int p = 0; p < NP; p++) {
                const int cur = p & 1;
                if (p + 1 < NP) loadB(p + 1, cur ^ 1);
#pragma unroll
                for (int sub = 0; sub < 2; sub++)
#pragma unroll
                    for (int mt = 0; mt < 2; mt++)
                        MMA_BF16(acc[mt][p * 2 + sub], Ahf[mt], Bhf[cur][2 * sub], Bhf[cur][2 * sub + 1]);
#pragma unroll
                for (int sub = 0; sub < 2; sub++)
#pragma unroll
                    for (int mt = 0; mt < 2; mt++)
                        MMA_BF16(acc[mt][p * 2 + sub], Ahf[mt], Blf[cur][2 * sub], Blf[cur][2 * sub + 1]);
#pragma unroll
                for (int sub = 0; sub < 2; sub++)
#pragma unroll
                    for (int mt = 0; mt < 2; mt++)
                        MMA_BF16(acc[mt][p * 2 + sub], Alf[mt], Bhf[cur][2 * sub], Bhf[cur][2 * sub + 1]);
            }
        }
    };

    const int nch = K / 32;
#pragma unroll
    for (int s = 0; s < NSTG - 1; s++) {
        cp_stage(s, s);
        CP_COMMIT();
    }
    for (int c = 0; c < nch; c++) {
        cp_wait<NSTG - 2>();
        __syncthreads();
        compute(c % NSTG);
        if (c + NSTG - 1 < nch) cp_stage(c + NSTG - 1, (c + NSTG - 1) % NSTG);
        CP_COMMIT();
    }

    if constexpr (ROPE) {
#pragma unroll
        for (int mt = 0; mt < 2; mt++) {
            int row0 = m0 + wm + mt * 16 + (lane >> 2);
#pragma unroll
            for (int nt = 0; nt < 4; nt++) {
                int col = n0 + wn + nt * 8 + (lane & 3) * 2;
                int sec = col / DIM;               // 0=q,1=k,2=v
                int hh  = (col % DIM) / HD;
                int i   = col % HD;                // < 32
#pragma unroll
                for (int t2 = 0; t2 < 2; t2++) {
                    int row = row0 + t2 * 8;
                    size_t base = ((size_t)hh * SEQ + row) * HD + i;
                    float a0 = acc[mt][nt][t2 * 2],     a1 = acc[mt][nt][t2 * 2 + 1];
                    float b0 = acc[mt][nt + 4][t2 * 2], b1 = acc[mt][nt + 4][t2 * 2 + 1];
                    uint32_t hi, lo;
                    if (sec == 2) {
                        split2(a0, a1, hi, lo);
                        *(uint32_t*)(g_vh + base) = hi;      *(uint32_t*)(g_vl + base) = lo;
                        split2(b0, b1, hi, lo);
                        *(uint32_t*)(g_vh + base + 32) = hi; *(uint32_t*)(g_vl + base + 32) = lo;
                    } else {
                        float2 cs = *(const float2*)(g_cos + row * 32 + i);
                        float2 sn = *(const float2*)(g_sin + row * 32 + i);
                        float ra0 = a0 * cs.x - b0 * sn.x, ra1 = a1 * cs.y - b1 * sn.y;
                        float rb0 = b0 * cs.x + a0 * sn.x, rb1 = b1 * cs.y + a1 * sn.y;
                        if (sec == 0) { ra0 *= 0.125f; ra1 *= 0.125f; rb0 *= 0.125f; rb1 *= 0.125f; }
                        __nv_bfloat16* dh = (sec == 0) ? g_qh : g_kh;
                        __nv_bfloat16* dl = (sec == 0) ? g_ql : g_kl;
                        split2(ra0, ra1, hi, lo);
                        *(uint32_t*)(dh + base) = hi;      *(uint32_t*)(dl + base) = lo;
                        split2(rb0, rb1, hi, lo);
                        *(uint32_t*)(dh + base + 32) = hi; *(uint32_t*)(dl + base + 32) = lo;
                    }
                }
            }
        }
    } else {
#pragma unroll
        for (int mt = 0; mt < 2; mt++) {
#pragma unroll
            for (int nt = 0; nt < NT; nt++) {
                int row = m0 + wm + mt * 16 + (lane >> 2);
                int col = n0 + wn + nt * 8 + (lane & 3) * 2;
                float* p0 = C + (size_t)row * N + col;
                float* p1 = C + (size_t)(row + 8) * N + col;
                *(float2*)p0 = make_float2(acc[mt][nt][0], acc[mt][nt][1]);
                *(float2*)p1 = make_float2(acc[mt][nt][2], acc[mt][nt][3]);
            }
        }
    }
}
#define GEMM_SMEM_128 (3 * 2 * (128 * 64 + 128 * 64))   // 98304, 3-stage
#define GEMM_SMEM_64  (4 * 2 * (64 * 64 + 128 * 64))    // 98304, 4-stage

// ============== tensor-core sliding-window attention (R13 version) ===========
#define APITCH 72
#define A_QH 0
#define A_QL (128 * APITCH)
#define A_KH (2 * 128 * APITCH)
#define A_KL (A_KH + 256 * APITCH)
#define A_VH (A_KH + 2 * 256 * APITCH)
#define A_VL (A_VH + 256 * APITCH)
#define ATTN_SMEM ((A_VL + 256 * APITCH) * 2)

__global__ void __launch_bounds__(256, 1) attn_mma_kernel()
{
    extern __shared__ __align__(16) char asm_[];
    __nv_bfloat16* sb = (__nv_bfloat16*)asm_;
    const uint32_t sbase = smem_u32(asm_);

    const int tid = threadIdx.x;
    const int w = tid >> 5;
    const int lane = tid & 31;
    const int h = blockIdx.y;
    const int tile = blockIdx.x;
    const int kbase = tile * 128 - WIN;

    // ---- stage Q hi/lo ----
    {
        const __nv_bfloat16* qsrc[2] = {g_qh, g_ql};
        const int qdst[2] = {A_QH, A_QL};
#pragma unroll
        for (int i = 0; i < 8; i++) {
            int mat = i >> 2;
            int f = (tid + i * 256) & 1023;
            int r = f >> 3, sg = f & 7;
            const __nv_bfloat16* src = qsrc[mat] +
                ((size_t)h * SEQ + tile * 128 + r) * HD + sg * 8;
            *(uint4*)(sb + qdst[mat] + r * APITCH + sg * 8) = *(const uint4*)src;
        }
    }
    // ---- stage K,V hi/lo, zero-fill OOB ----
    {
        const __nv_bfloat16* kvsrc[4] = {g_kh, g_kl, g_vh, g_vl};
        const int kvdst[4] = {A_KH, A_KL, A_VH, A_VL};
#pragma unroll
        for (int i = 0; i < 32; i++) {
            int mat = i >> 3;
            int f = (tid + i * 256) & 2047;
            int r = f >> 3, sg = f & 7;
            int key = kbase + r;
            uint4 val = make_uint4(0u, 0u, 0u, 0u);
            if (key >= 0 && key < SEQ)
                val = *(const uint4*)(kvsrc[mat] + ((size_t)h * SEQ + key) * HD + sg * 8);
            *(uint4*)(sb + kvdst[mat] + r * APITCH + sg * 8) = val;
        }
    }
    __syncthreads();

    float m0 = -1e30f, m1 = -1e30f, l0 = 0.f, l1 = 0.f;
    float O[8][4];
#pragma unroll
    for (int j = 0; j < 8; j++)
#pragma unroll
        for (int t = 0; t < 4; t++) O[j][t] = 0.f;

    const int q0 = tile * 128 + w * 16 + (lane >> 2);

    for (int c = 0; c < 2; c++) {
        int lo_col = w * 16 - 128 * c;
        int hi_col = lo_col + 143;
        int t_lo = lo_col < 0 ? 0 : (lo_col >> 4);
        int t_hi = (hi_col >> 4) < 7 ? (hi_col >> 4) : 7;

        float S[16][4];
#pragma unroll
        for (int b = 0; b < 16; b++)
#pragma unroll
            for (int t = 0; t < 4; t++) S[b][t] = 0.f;

#pragma unroll
        for (int ks = 0; ks < 4; ks++) {
            uint32_t Ah[4], Al[4];
            uint32_t aoff = (uint32_t)((w * 16 + (lane & 15)) * APITCH + ks * 16 + (lane >> 4) * 8) * 2;
            LDSM4(Ah, sbase + A_QH * 2 + aoff);
            LDSM4(Al, sbase + A_QL * 2 + aoff);
#pragma unroll
            for (int g = 0; g < 8; g++) {
                if (g < t_lo || g > t_hi) continue;
                int quad = lane >> 3, l8 = lane & 7;
                int n = c * 128 + g * 16 + ((quad >> 1) & 1) * 8 + l8;
                int cc = ks * 16 + (quad & 1) * 8;
                uint32_t boff = (uint32_t)(n * APITCH + cc) * 2;
                uint32_t Bh[4], Bl[4];
                LDSM4(Bh, sbase + A_KH * 2 + boff);
                LDSM4(Bl, sbase + A_KL * 2 + boff);
#pragma unroll
                for (int sub = 0; sub < 2; sub++)
                    MMA_BF16(S[g * 2 + sub], Ah, Bh[2 * sub], Bh[2 * sub + 1]);
#pragma unroll
                for (int sub = 0; sub < 2; sub++)
                    MMA_BF16(S[g * 2 + sub], Ah, Bl[2 * sub], Bl[2 * sub + 1]);
#pragma unroll
                for (int sub = 0; sub < 2; sub++)
                    MMA_BF16(S[g * 2 + sub], Al, Bh[2 * sub], Bh[2 * sub + 1]);
            }
        }

        float mc0 = -1e30f, mc1 = -1e30f;
#pragma unroll
        for (int b = 0; b < 16; b++) {
            if ((b >> 1) < t_lo || (b >> 1) > t_hi) continue;
            int k0g = kbase + c * 128 + b * 8 + (lane & 3) * 2;
#pragma unroll
            for (int t = 0; t < 4; t++) {
                int kg = k0g + (t & 1);
                int qq = q0 + (t >> 1) * 8;
                bool ok = (kg >= 0) && (kg < SEQ) && (kg >= qq - WIN) && (kg <= qq + WIN);
                if (!ok) S[b][t] = -1e30f;
            }
            mc0 = fmaxf(mc0, fmaxf(S[b][0], S[b][1]));
            mc1 = fmaxf(mc1, fmaxf(S[b][2], S[b][3]));
        }
        mc0 = fmaxf(mc0, __shfl_xor_sync(0xffffffffu, mc0, 1));
        mc0 = fmaxf(mc0, __shfl_xor_sync(0xffffffffu, mc0, 2));
        mc1 = fmaxf(mc1, __shfl_xor_sync(0xffffffffu, mc1, 1));
        mc1 = fmaxf(mc1, __shfl_xor_sync(0xffffffffu, mc1, 2));

        float nm0 = fmaxf(m0, mc0), nm1 = fmaxf(m1, mc1);
        float f0 = __expf(m0 - nm0), f1 = __expf(m1 - nm1);
        l0 *= f0; l1 *= f1;
#pragma unroll
        for (int j = 0; j < 8; j++) {
            O[j][0] *= f0; O[j][1] *= f0;
            O[j][2] *= f1; O[j][3] *= f1;
        }
        m0 = nm0; m1 = nm1;

        uint32_t Ph[16][2], Pl[16][2];
        float s0 = 0.f, s1 = 0.f;
#pragma unroll
        for (int b = 0; b < 16; b++) {
            if ((b >> 1) < t_lo || (b >> 1) > t_hi) continue;
            float p0 = __expf(S[b][0] - m0), p1 = __expf(S[b][1] - m0);
            float p2 = __expf(S[b][2] - m1), p3 = __expf(S[b][3] - m1);
            s0 += p0 + p1; s1 += p2 + p3;
            split2(p0, p1, Ph[b][0], Pl[b][0]);
            split2(p2, p3, Ph[b][1], Pl[b][1]);
        }
        s0 += __shfl_xor_sync(0xffffffffu, s0, 1);
        s0 += __shfl_xor_sync(0xffffffffu, s0, 2);
        s1 += __shfl_xor_sync(0xffffffffu, s1, 1);
        s1 += __shfl_xor_sync(0xffffffffu, s1, 2);
        l0 += s0; l1 += s1;

#pragma unroll
        for (int kk = 0; kk < 8; kk++) {
            if (kk < t_lo || kk > t_hi) continue;
            uint32_t Aph[4] = {Ph[2 * kk][0], Ph[2 * kk][1], Ph[2 * kk + 1][0], Ph[2 * kk + 1][1]};
            uint32_t Apl[4] = {Pl[2 * kk][0], Pl[2 * kk][1], Pl[2 * kk + 1][0], Pl[2 * kk + 1][1]};
            int krow = c * 128 + kk * 16 + (lane & 7) + ((lane >> 3) & 1) * 8;
#pragma unroll
            for (int g = 0; g < 4; g++) {
                uint32_t voff = (uint32_t)(krow * APITCH + g * 16 + (lane >> 4) * 8) * 2;
                uint32_t Bh[4], Bl[4];
                LDSM4T(Bh, sbase + A_VH * 2 + voff);
                LDSM4T(Bl, sbase + A_VL * 2 + voff);
#pragma unroll
                for (int sub = 0; sub < 2; sub++)
                    MMA_BF16(O[g * 2 + sub], Aph, Bh[2 * sub], Bh[2 * sub + 1]);
#pragma unroll
                for (int sub = 0; sub < 2; sub++)
                    MMA_BF16(O[g * 2 + sub], Aph, Bl[2 * sub], Bl[2 * sub + 1]);
#pragma unroll
                for (int sub = 0; sub < 2; sub++)
                    MMA_BF16(O[g * 2 + sub], Apl, Bh[2 * sub], Bh[2 * sub + 1]);
            }
        }
    }

    float i0 = 1.f / l0, i1 = 1.f / l1;
    size_t o0 = (size_t)q0 * DIM + h * HD;
    size_t o1 = (size_t)(q0 + 8) * DIM + h * HD;
#pragma unroll
    for (int j = 0; j < 8; j++) {
        int col = j * 8 + (lane & 3) * 2;
        uint32_t hi, lo;
        split2(O[j][0] * i0, O[j][1] * i0, hi, lo);
        *(uint32_t*)(g_aoh + o0 + col) = hi;
        *(uint32_t*)(g_aol + o0 + col) = lo;
        split2(O[j][2] * i1, O[j][3] * i1, hi, lo);
        *(uint32_t*)(g_aoh + o1 + col) = hi;
        *(uint32_t*)(g_aol + o1 + col) = lo;
    }
}

// ---------------- launch -----------------------------------------------------
extern "C" void kernel_launch(void* const* d_in, const int* in_sizes, int n_in,
                              void* d_out, int out_size)
{
    const float* x    = (const float*)d_in[0];
    const int*   pos  = (const int*)  d_in[1];
    const float* wqkv = (const float*)d_in[2];
    const float* wo   = (const float*)d_in[3];
    float*       out  = (float*)d_out;

    __nv_bfloat16 *pxh, *pxl, *pwqh, *pwql, *pwoh, *pwol, *paoh, *paol;
    cudaGetSymbolAddress((void**)&pxh,  g_xh);
    cudaGetSymbolAddress((void**)&pxl,  g_xl);
    cudaGetSymbolAddress((void**)&pwqh, g_wqh);
    cudaGetSymbolAddress((void**)&pwql, g_wql);
    cudaGetSymbolAddress((void**)&pwoh, g_woh);
    cudaGetSymbolAddress((void**)&pwol, g_wol);
    cudaGetSymbolAddress((void**)&paoh, g_aoh);
    cudaGetSymbolAddress((void**)&paol, g_aol);

    cudaFuncSetAttribute((const void*)gemm_bf16_kernel<128, true, 3>,
                         cudaFuncAttributeMaxDynamicSharedMemorySize, GEMM_SMEM_128);
    cudaFuncSetAttribute((const void*)gemm_bf16_kernel<64, false, 4>,
                         cudaFuncAttributeMaxDynamicSharedMemorySize, GEMM_SMEM_64);
    cudaFuncSetAttribute(attn_mma_kernel, cudaFuncAttributeMaxDynamicSharedMemorySize, ATTN_SMEM);

    // 0) fused preprocessing: splits + RoPE table, ONE launch
    preproc_kernel<<<(NPRE + 255) / 256, 256>>>(x, wqkv, wo, pos);

    // 1) QKV projection + fused table-RoPE/split -> q,k,v bf16 hi/lo directly
    gemm_bf16_kernel<128, true, 3><<<dim3(QKVDIM / 128, SEQ / 128), 256, GEMM_SMEM_128>>>(
        pxh, pxl, pwqh, pwql, nullptr, SEQ, QKVDIM, DIM);

    // 2) sliding-window attention (tensor cores), writes bf16 hi/lo ao
    attn_mma_kernel<<<dim3(SEQ / 128, NH), 256, ATTN_SMEM>>>();

    // 3) output projection (4-stage pipeline): [4096,768] x [768,768]^T
    gemm_bf16_kernel<64, false, 4><<<dim3(DIM / 128, SEQ / 64), 256, GEMM_SMEM_64>>>(
        paoh, paol, pwoh, pwol, out, SEQ, DIM, DIM);
}

// round 17
// speedup vs baseline: 1.0678x; 1.0678x over previous
#include <cuda_runtime.h>
#include <cuda_bf16.h>
#include <cuda_fp16.h>
#include <cstdint>

#define SEQ      4096
#define DIM      768
#define NH       12
#define HD       64
#define QKVDIM   2304
#define WIN      64      // WINDOW/2

// ---------------- scratch (device globals; no allocation allowed) -----------
__device__ __nv_bfloat16 g_xh[SEQ * DIM],    g_xl[SEQ * DIM];
__device__ __nv_bfloat16 g_wqh[QKVDIM * DIM], g_wql[QKVDIM * DIM];
__device__ __half        g_wo16[DIM * DIM];
__device__ __nv_bfloat16 g_qh[NH * SEQ * HD], g_ql[NH * SEQ * HD];
__device__ __nv_bfloat16 g_kh[NH * SEQ * HD], g_kl[NH * SEQ * HD];
__device__ __nv_bfloat16 g_vh[NH * SEQ * HD], g_vl[NH * SEQ * HD];
__device__ __half        g_aoh[SEQ * DIM],   g_aol[SEQ * DIM];   // fp16 hi/lo
__device__ float g_cos[SEQ * 32], g_sin[SEQ * 32];   // RoPE tables

// =================== common helpers ==========================================
__device__ __forceinline__ uint32_t smem_u32(const void* p) {
    uint32_t a;
    asm("{ .reg .u64 t; cvta.to.shared.u64 t, %1; cvt.u32.u64 %0, t; }" : "=r"(a) : "l"(p));
    return a;
}
#define LDSM4(r, addr) \
    asm volatile("ldmatrix.sync.aligned.m8n8.x4.shared.b16 {%0,%1,%2,%3}, [%4];" \
        : "=r"((r)[0]), "=r"((r)[1]), "=r"((r)[2]), "=r"((r)[3]) : "r"(addr))
#define LDSM4T(r, addr) \
    asm volatile("ldmatrix.sync.aligned.m8n8.x4.trans.shared.b16 {%0,%1,%2,%3}, [%4];" \
        : "=r"((r)[0]), "=r"((r)[1]), "=r"((r)[2]), "=r"((r)[3]) : "r"(addr))
#define MMA_BF16(d, a, b0, b1) \
    asm volatile("mma.sync.aligned.m16n8k16.row.col.f32.bf16.bf16.f32 " \
        "{%0,%1,%2,%3}, {%4,%5,%6,%7}, {%8,%9}, {%0,%1,%2,%3};" \
        : "+f"((d)[0]), "+f"((d)[1]), "+f"((d)[2]), "+f"((d)[3]) \
        : "r"((a)[0]), "r"((a)[1]), "r"((a)[2]), "r"((a)[3]), "r"(b0), "r"(b1))
#define MMA_F16(d, a, b0, b1) \
    asm volatile("mma.sync.aligned.m16n8k16.row.col.f32.f16.f16.f32 " \
        "{%0,%1,%2,%3}, {%4,%5,%6,%7}, {%8,%9}, {%0,%1,%2,%3};" \
        : "+f"((d)[0]), "+f"((d)[1]), "+f"((d)[2]), "+f"((d)[3]) \
        : "r"((a)[0]), "r"((a)[1]), "r"((a)[2]), "r"((a)[3]), "r"(b0), "r"(b1))
#define CP16(dst, src) \
    asm volatile("cp.async.cg.shared.global [%0], [%1], 16;" :: "r"(dst), "l"(src))
#define CP_COMMIT() asm volatile("cp.async.commit_group;" ::: "memory")
template<int N>
__device__ __forceinline__ void cp_wait() {
    asm volatile("cp.async.wait_group %0;" :: "n"(N) : "memory");
}

__device__ __forceinline__ uint32_t pack_bf2(__nv_bfloat16 a, __nv_bfloat16 b) {
    __nv_bfloat162 t(a, b);
    return *reinterpret_cast<uint32_t*>(&t);
}
__device__ __forceinline__ void split2(float x, float y, uint32_t& hi, uint32_t& lo) {
    __nv_bfloat16 hx = __float2bfloat16(x);
    __nv_bfloat16 hy = __float2bfloat16(y);
    __nv_bfloat16 lx = __float2bfloat16(x - __bfloat162float(hx));
    __nv_bfloat16 ly = __float2bfloat16(y - __bfloat162float(hy));
    hi = pack_bf2(hx, hy);
    lo = pack_bf2(lx, ly);
}
// fp16 hi/lo split (packed pairs)
__device__ __forceinline__ void split2h(float x, float y, uint32_t& hi, uint32_t& lo) {
    __half hx = __float2half_rn(x), hy = __float2half_rn(y);
    __half lx = __float2half_rn(x - __half2float(hx));
    __half ly = __float2half_rn(y - __half2float(hy));
    __half2 th(hx, hy), tl(lx, ly);
    hi = *reinterpret_cast<uint32_t*>(&th);
    lo = *reinterpret_cast<uint32_t*>(&tl);
}
// swizzled smem byte offset, 64B rows: (row r, 16B chunk c in 0..3)
__device__ __forceinline__ uint32_t swz64(int r, int c) {
    return (uint32_t)(r * 64 + ((c ^ ((r >> 1) & 3)) * 16));
}

// =================== fused preprocessing =====================================
#define NX  (SEQ * DIM / 4)
#define NWQ (QKVDIM * DIM / 4)
#define NWO (DIM * DIM / 4)
#define NRT (SEQ * 32)
#define NPRE (NX + NWQ + NWO + NRT)

__global__ void preproc_kernel(const float* __restrict__ x,
                               const float* __restrict__ wqkv,
                               const float* __restrict__ wo,
                               const int* __restrict__ posids)
{
    int g = blockIdx.x * blockDim.x + threadIdx.x;
    if (g >= NPRE) return;

    if (g < NX + NWQ) {                      // bf16 hi/lo splits (x, wqkv)
        const float* src;
        __nv_bfloat16 *hi, *lo;
        int i;
        if (g < NX) { src = x;    hi = g_xh;  lo = g_xl;  i = g; }
        else        { src = wqkv; hi = g_wqh; lo = g_wql; i = g - NX; }
        i *= 4;
        float4 v = *(const float4*)(src + i);
        uint2 h, l;
        split2(v.x, v.y, h.x, l.x);
        split2(v.z, v.w, h.y, l.y);
        *(uint2*)(hi + i) = h;
        *(uint2*)(lo + i) = l;
    } else if (g < NX + NWQ + NWO) {         // wo -> single fp16
        int i = (g - NX - NWQ) * 4;
        float4 v = *(const float4*)(wo + i);
        __half2 a(__float2half_rn(v.x), __float2half_rn(v.y));
        __half2 b(__float2half_rn(v.z), __float2half_rn(v.w));
        uint2 p = make_uint2(*reinterpret_cast<uint32_t*>(&a),
                             *reinterpret_cast<uint32_t*>(&b));
        *(uint2*)(g_wo16 + i) = p;
    } else {                                  // RoPE table
        int idx = g - NX - NWQ - NWO;
        int ri = idx & 31, s = idx >> 5;
        float f = (float)posids[s] * powf(10000.f, -(float)ri / 32.f);
        g_cos[idx] = cosf(f);
        g_sin[idx] = sinf(f);
    }
}

// =================== bf16 HMMA GEMM (QKV), 3-MMA compensation ================
// BK=32, 256 threads, 3-stage cp.async pipeline, 2 CTAs/SM, fused RoPE epilogue.
__global__ void __launch_bounds__(256, 2) gemm_qkv_kernel(
    const __nv_bfloat16* __restrict__ Ah, const __nv_bfloat16* __restrict__ Al,
    const __nv_bfloat16* __restrict__ Bh, const __nv_bfloat16* __restrict__ Bl,
    int M, int N, int K)
{
    constexpr int NT  = 8;
    constexpr int TA  = 128 * 64;
    constexpr int TB  = 128 * 64;
    constexpr int STG = 2 * (TA + TB);
    constexpr int NSTG = 3;

    extern __shared__ char smem[];
    const uint32_t sb0 = smem_u32(smem);

    const int tid  = threadIdx.x;
    const int wid  = tid >> 5;
    const int lane = tid & 31;
    const int m0 = blockIdx.y * 128;
    const int n0 = blockIdx.x * 128;
    const int wm = (wid & 3) * 32;
    const int wn = (wid >> 2) * 64;

    const __nv_bfloat16* Ahb = Ah + (size_t)m0 * K;
    const __nv_bfloat16* Alb = Al + (size_t)m0 * K;
    const __nv_bfloat16* Bhb = Bh + (size_t)n0 * K;
    const __nv_bfloat16* Blb = Bl + (size_t)n0 * K;

    auto cp_stage = [&](int c, int s) {
        const int kc = c * 32;
        const uint32_t base = sb0 + s * STG;
#pragma unroll
        for (int i = 0; i < 2; i++) {
            int f = tid + i * 256;
            int r = f >> 2, sg = f & 3;
            uint32_t off = swz64(r, sg);
            const size_t go = (size_t)r * K + kc + sg * 8;
            CP16(base + off,      Ahb + go);
            CP16(base + TA + off, Alb + go);
            CP16(base + 2 * TA + off,      Bhb + go);
            CP16(base + 2 * TA + TB + off, Blb + go);
        }
    };

    float acc[2][NT][4];
#pragma unroll
    for (int i = 0; i < 2; i++)
#pragma unroll
        for (int j = 0; j < NT; j++)
#pragma unroll
            for (int t = 0; t < 4; t++) acc[i][j][t] = 0.f;

    auto compute = [&](int s) {
        const uint32_t base = sb0 + s * STG;
        const uint32_t aHi = base, aLo = base + TA;
        const uint32_t bHi = base + 2 * TA, bLo = base + 2 * TA + TB;
#pragma unroll
        for (int ks = 0; ks < 2; ks++) {
            uint32_t Ahf[2][4], Alf[2][4];
#pragma unroll
            for (int mt = 0; mt < 2; mt++) {
                int r = wm + mt * 16 + (lane & 15);
                int ch = ks * 2 + (lane >> 4);
                uint32_t off = swz64(r, ch);
                LDSM4(Ahf[mt], aHi + off);
                LDSM4(Alf[mt], aLo + off);
            }
#pragma unroll
            for (int p = 0; p < NT / 2; p++) {
                int quad = lane >> 3, l8 = lane & 7;
                int n = wn + p * 16 + (quad >> 1) * 8 + l8;
                int ch = ks * 2 + (quad & 1);
                uint32_t off = swz64(n, ch);
                uint32_t Bhf[4], Blf[4];
                LDSM4(Bhf, bHi + off);
                LDSM4(Blf, bLo + off);
#pragma unroll
                for (int sub = 0; sub < 2; sub++)
#pragma unroll
                    for (int mt = 0; mt < 2; mt++)
                        MMA_BF16(acc[mt][p * 2 + sub], Ahf[mt], Bhf[2 * sub], Bhf[2 * sub + 1]);
#pragma unroll
                for (int sub = 0; sub < 2; sub++)
#pragma unroll
                    for (int mt = 0; mt < 2; mt++)
                        MMA_BF16(acc[mt][p * 2 + sub], Ahf[mt], Blf[2 * sub], Blf[2 * sub + 1]);
#pragma unroll
                for (int sub = 0; sub < 2; sub++)
#pragma unroll
                    for (int mt = 0; mt < 2; mt++)
                        MMA_BF16(acc[mt][p * 2 + sub], Alf[mt], Bhf[2 * sub], Bhf[2 * sub + 1]);
            }
        }
    };

    const int nch = K / 32;
#pragma unroll
    for (int s = 0; s < NSTG - 1; s++) { cp_stage(s, s); CP_COMMIT(); }
    for (int c = 0; c < nch; c++) {
        cp_wait<NSTG - 2>();
        __syncthreads();
        compute(c % NSTG);
        if (c + NSTG - 1 < nch) cp_stage(c + NSTG - 1, (c + NSTG - 1) % NSTG);
        CP_COMMIT();
    }

    // fused RoPE epilogue
#pragma unroll
    for (int mt = 0; mt < 2; mt++) {
        int row0 = m0 + wm + mt * 16 + (lane >> 2);
#pragma unroll
        for (int nt = 0; nt < 4; nt++) {
            int col = n0 + wn + nt * 8 + (lane & 3) * 2;
            int sec = col / DIM;               // 0=q,1=k,2=v
            int hh  = (col % DIM) / HD;
            int i   = col % HD;                // < 32
#pragma unroll
            for (int t2 = 0; t2 < 2; t2++) {
                int row = row0 + t2 * 8;
                size_t base = ((size_t)hh * SEQ + row) * HD + i;
                float a0 = acc[mt][nt][t2 * 2],     a1 = acc[mt][nt][t2 * 2 + 1];
                float b0 = acc[mt][nt + 4][t2 * 2], b1 = acc[mt][nt + 4][t2 * 2 + 1];
                uint32_t hi, lo;
                if (sec == 2) {
                    split2(a0, a1, hi, lo);
                    *(uint32_t*)(g_vh + base) = hi;      *(uint32_t*)(g_vl + base) = lo;
                    split2(b0, b1, hi, lo);
                    *(uint32_t*)(g_vh + base + 32) = hi; *(uint32_t*)(g_vl + base + 32) = lo;
                } else {
                    float2 cs = *(const float2*)(g_cos + row * 32 + i);
                    float2 sn = *(const float2*)(g_sin + row * 32 + i);
                    float ra0 = a0 * cs.x - b0 * sn.x, ra1 = a1 * cs.y - b1 * sn.y;
                    float rb0 = b0 * cs.x + a0 * sn.x, rb1 = b1 * cs.y + a1 * sn.y;
                    if (sec == 0) { ra0 *= 0.125f; ra1 *= 0.125f; rb0 *= 0.125f; rb1 *= 0.125f; }
                    __nv_bfloat16* dh = (sec == 0) ? g_qh : g_kh;
                    __nv_bfloat16* dl = (sec == 0) ? g_ql : g_kl;
                    split2(ra0, ra1, hi, lo);
                    *(uint32_t*)(dh + base) = hi;      *(uint32_t*)(dl + base) = lo;
                    split2(rb0, rb1, hi, lo);
                    *(uint32_t*)(dh + base + 32) = hi; *(uint32_t*)(dl + base + 32) = lo;
                }
            }
        }
    }
}
#define GEMM_SMEM_QKV (3 * 2 * (128 * 64 + 128 * 64))   // 98304

// =================== fp16 2-term out-projection GEMM =========================
// C = (Ah+Al) * B^T with A fp16 hi/lo, B single fp16. BM=64, BK=32, 4-stage,
// 3 CTAs/SM (smem 64 KB). 2 MMAs per product instead of 3.
__global__ void __launch_bounds__(256, 3) gemm_out_kernel(
    const __half* __restrict__ Ah, const __half* __restrict__ Al,
    const __half* __restrict__ B,
    float* __restrict__ C, int M, int N, int K)
{
    constexpr int TA  = 64 * 64;            // 4096 B
    constexpr int TB  = 128 * 64;           // 8192 B
    constexpr int STG = 2 * TA + TB;        // 16384 B
    constexpr int NSTG = 4;

    extern __shared__ char smem[];
    const uint32_t sb0 = smem_u32(smem);

    const int tid  = threadIdx.x;
    const int wid  = tid >> 5;
    const int lane = tid & 31;
    const int m0 = blockIdx.y * 64;
    const int n0 = blockIdx.x * 128;
    const int wm = (wid & 1) * 32;
    const int wn = (wid >> 1) * 32;

    const __half* Ahb = Ah + (size_t)m0 * K;
    const __half* Alb = Al + (size_t)m0 * K;
    const __half* Bb  = B  + (size_t)n0 * K;

    auto cp_stage = [&](int c, int s) {
        const int kc = c * 32;
        const uint32_t base = sb0 + s * STG;
        {   // A hi/lo: 64 rows x 4 chunks = 256 slots
            int r = tid >> 2, sg = tid & 3;
            uint32_t off = swz64(r, sg);
            const size_t go = (size_t)r * K + kc + sg * 8;
            CP16(base + off,      Ahb + go);
            CP16(base + TA + off, Alb + go);
        }
#pragma unroll
        for (int i = 0; i < 2; i++) {   // B: 128 rows x 4 chunks
            int f = tid + i * 256;
            int r = f >> 2, sg = f & 3;
            uint32_t off = swz64(r, sg);
            CP16(base + 2 * TA + off, Bb + (size_t)r * K + kc + sg * 8);
        }
    };

    float acc[2][4][4];
#pragma unroll
    for (int i = 0; i < 2; i++)
#pragma unroll
        for (int j = 0; j < 4; j++)
#pragma unroll
            for (int t = 0; t < 4; t++) acc[i][j][t] = 0.f;

    auto compute = [&](int s) {
        const uint32_t base = sb0 + s * STG;
        const uint32_t aHi = base, aLo = base + TA, bB = base + 2 * TA;
#pragma unroll
        for (int ks = 0; ks < 2; ks++) {
            uint32_t Ahf[2][4], Alf[2][4];
#pragma unroll
            for (int mt = 0; mt < 2; mt++) {
                int r = wm + mt * 16 + (lane & 15);
                int ch = ks * 2 + (lane >> 4);
                uint32_t off = swz64(r, ch);
                LDSM4(Ahf[mt], aHi + off);
                LDSM4(Alf[mt], aLo + off);
            }
#pragma unroll
            for (int p = 0; p < 2; p++) {
                int quad = lane >> 3, l8 = lane & 7;
                int n = wn + p * 16 + (quad >> 1) * 8 + l8;
                int ch = ks * 2 + (quad & 1);
                uint32_t Bf[4];
                LDSM4(Bf, bB + swz64(n, ch));
#pragma unroll
                for (int sub = 0; sub < 2; sub++)
#pragma unroll
                    for (int mt = 0; mt < 2; mt++)
                        MMA_F16(acc[mt][p * 2 + sub], Ahf[mt], Bf[2 * sub], Bf[2 * sub + 1]);
#pragma unroll
                for (int sub = 0; sub < 2; sub++)
#pragma unroll
                    for (int mt = 0; mt < 2; mt++)
                        MMA_F16(acc[mt][p * 2 + sub], Alf[mt], Bf[2 * sub], Bf[2 * sub + 1]);
            }
        }
    };

    const int nch = K / 32;
#pragma unroll
    for (int s = 0; s < NSTG - 1; s++) { cp_stage(s, s); CP_COMMIT(); }
    for (int c = 0; c < nch; c++) {
        cp_wait<NSTG - 2>();
        __syncthreads();
        compute(c % NSTG);
        if (c + NSTG - 1 < nch) cp_stage(c + NSTG - 1, (c + NSTG - 1) % NSTG);
        CP_COMMIT();
    }

#pragma unroll
    for (int mt = 0; mt < 2; mt++) {
#pragma unroll
        for (int nt = 0; nt < 4; nt++) {
            int row = m0 + wm + mt * 16 + (lane >> 2);
            int col = n0 + wn + nt * 8 + (lane & 3) * 2;
            float* p0 = C + (size_t)row * N + col;
            float* p1 = C + (size_t)(row + 8) * N + col;
            *(float2*)p0 = make_float2(acc[mt][nt][0], acc[mt][nt][1]);
            *(float2*)p1 = make_float2(acc[mt][nt][2], acc[mt][nt][3]);
        }
    }
}
#define GEMM_SMEM_OUT (4 * (2 * 64 * 64 + 128 * 64))    // 65536

// ============== tensor-core sliding-window attention (R13/R15) ===============
#define APITCH 72
#define A_QH 0
#define A_QL (128 * APITCH)
#define A_KH (2 * 128 * APITCH)
#define A_KL (A_KH + 256 * APITCH)
#define A_VH (A_KH + 2 * 256 * APITCH)
#define A_VL (A_VH + 256 * APITCH)
#define ATTN_SMEM ((A_VL + 256 * APITCH) * 2)

__global__ void __launch_bounds__(256, 1) attn_mma_kernel()
{
    extern __shared__ __align__(16) char asm_[];
    __nv_bfloat16* sb = (__nv_bfloat16*)asm_;
    const uint32_t sbase = smem_u32(asm_);

    const int tid = threadIdx.x;
    const int w = tid >> 5;
    const int lane = tid & 31;
    const int h = blockIdx.y;
    const int tile = blockIdx.x;
    const int kbase = tile * 128 - WIN;

    // ---- stage Q hi/lo ----
    {
        const __nv_bfloat16* qsrc[2] = {g_qh, g_ql};
        const int qdst[2] = {A_QH, A_QL};
#pragma unroll
        for (int i = 0; i < 8; i++) {
            int mat = i >> 2;
            int f = (tid + i * 256) & 1023;
            int r = f >> 3, sg = f & 7;
            const __nv_bfloat16* src = qsrc[mat] +
                ((size_t)h * SEQ + tile * 128 + r) * HD + sg * 8;
            *(uint4*)(sb + qdst[mat] + r * APITCH + sg * 8) = *(const uint4*)src;
        }
    }
    // ---- stage K,V hi/lo, zero-fill OOB ----
    {
        const __nv_bfloat16* kvsrc[4] = {g_kh, g_kl, g_vh, g_vl};
        const int kvdst[4] = {A_KH, A_KL, A_VH, A_VL};
#pragma unroll
        for (int i = 0; i < 32; i++) {
            int mat = i >> 3;
            int f = (tid + i * 256) & 2047;
            int r = f >> 3, sg = f & 7;
            int key = kbase + r;
            uint4 val = make_uint4(0u, 0u, 0u, 0u);
            if (key >= 0 && key < SEQ)
                val = *(const uint4*)(kvsrc[mat] + ((size_t)h * SEQ + key) * HD + sg * 8);
            *(uint4*)(sb + kvdst[mat] + r * APITCH + sg * 8) = val;
        }
    }
    __syncthreads();

    float m0 = -1e30f, m1 = -1e30f, l0 = 0.f, l1 = 0.f;
    float O[8][4];
#pragma unroll
    for (int j = 0; j < 8; j++)
#pragma unroll
        for (int t = 0; t < 4; t++) O[j][t] = 0.f;

    const int q0 = tile * 128 + w * 16 + (lane >> 2);

    for (int c = 0; c < 2; c++) {
        int lo_col = w * 16 - 128 * c;
        int hi_col = lo_col + 143;
        int t_lo = lo_col < 0 ? 0 : (lo_col >> 4);
        int t_hi = (hi_col >> 4) < 7 ? (hi_col >> 4) : 7;

        float S[16][4];
#pragma unroll
        for (int b = 0; b < 16; b++)
#pragma unroll
            for (int t = 0; t < 4; t++) S[b][t] = 0.f;

#pragma unroll
        for (int ks = 0; ks < 4; ks++) {
            uint32_t Ah[4], Al[4];
            uint32_t aoff = (uint32_t)((w * 16 + (lane & 15)) * APITCH + ks * 16 + (lane >> 4) * 8) * 2;
            LDSM4(Ah, sbase + A_QH * 2 + aoff);
            LDSM4(Al, sbase + A_QL * 2 + aoff);
#pragma unroll
            for (int g = 0; g < 8; g++) {
                if (g < t_lo || g > t_hi) continue;
                int quad = lane >> 3, l8 = lane & 7;
                int n = c * 128 + g * 16 + ((quad >> 1) & 1) * 8 + l8;
                int cc = ks * 16 + (quad & 1) * 8;
                uint32_t boff = (uint32_t)(n * APITCH + cc) * 2;
                uint32_t Bh[4], Bl[4];
                LDSM4(Bh, sbase + A_KH * 2 + boff);
                LDSM4(Bl, sbase + A_KL * 2 + boff);
#pragma unroll
                for (int sub = 0; sub < 2; sub++)
                    MMA_BF16(S[g * 2 + sub], Ah, Bh[2 * sub], Bh[2 * sub + 1]);
#pragma unroll
                for (int sub = 0; sub < 2; sub++)
                    MMA_BF16(S[g * 2 + sub], Ah, Bl[2 * sub], Bl[2 * sub + 1]);
#pragma unroll
                for (int sub = 0; sub < 2; sub++)
                    MMA_BF16(S[g * 2 + sub], Al, Bh[2 * sub], Bh[2 * sub + 1]);
            }
        }

        float mc0 = -1e30f, mc1 = -1e30f;
#pragma unroll
        for (int b = 0; b < 16; b++) {
            if ((b >> 1) < t_lo || (b >> 1) > t_hi) continue;
            int k0g = kbase + c * 128 + b * 8 + (lane & 3) * 2;
#pragma unroll
            for (int t = 0; t < 4; t++) {
                int kg = k0g + (t & 1);
                int qq = q0 + (t >> 1) * 8;
                bool ok = (kg >= 0) && (kg < SEQ) && (kg >= qq - WIN) && (kg <= qq + WIN);
                if (!ok) S[b][t] = -1e30f;
            }
            mc0 = fmaxf(mc0, fmaxf(S[b][0], S[b][1]));
            mc1 = fmaxf(mc1, fmaxf(S[b][2], S[b][3]));
        }
        mc0 = fmaxf(mc0, __shfl_xor_sync(0xffffffffu, mc0, 1));
        mc0 = fmaxf(mc0, __shfl_xor_sync(0xffffffffu, mc0, 2));
        mc1 = fmaxf(mc1, __shfl_xor_sync(0xffffffffu, mc1, 1));
        mc1 = fmaxf(mc1, __shfl_xor_sync(0xffffffffu, mc1, 2));

        float nm0 = fmaxf(m0, mc0), nm1 = fmaxf(m1, mc1);
        float f0 = __expf(m0 - nm0), f1 = __expf(m1 - nm1);
        l0 *= f0; l1 *= f1;
#pragma unroll
        for (int j = 0; j < 8; j++) {
            O[j][0] *= f0; O[j][1] *= f0;
            O[j][2] *= f1; O[j][3] *= f1;
        }
        m0 = nm0; m1 = nm1;

        uint32_t Ph[16][2], Pl[16][2];
        float s0 = 0.f, s1 = 0.f;
#pragma unroll
        for (int b = 0; b < 16; b++) {
            if ((b >> 1) < t_lo || (b >> 1) > t_hi) continue;
            float p0 = __expf(S[b][0] - m0), p1 = __expf(S[b][1] - m0);
            float p2 = __expf(S[b][2] - m1), p3 = __expf(S[b][3] - m1);
            s0 += p0 + p1; s1 += p2 + p3;
            split2(p0, p1, Ph[b][0], Pl[b][0]);
            split2(p2, p3, Ph[b][1], Pl[b][1]);
        }
        s0 += __shfl_xor_sync(0xffffffffu, s0, 1);
        s0 += __shfl_xor_sync(0xffffffffu, s0, 2);
        s1 += __shfl_xor_sync(0xffffffffu, s1, 1);
        s1 += __shfl_xor_sync(0xffffffffu, s1, 2);
        l0 += s0; l1 += s1;

#pragma unroll
        for (int kk = 0; kk < 8; kk++) {
            if (kk < t_lo || kk > t_hi) continue;
            uint32_t Aph[4] = {Ph[2 * kk][0], Ph[2 * kk][1], Ph[2 * kk + 1][0], Ph[2 * kk + 1][1]};
            uint32_t Apl[4] = {Pl[2 * kk][0], Pl[2 * kk][1], Pl[2 * kk + 1][0], Pl[2 * kk + 1][1]};
            int krow = c * 128 + kk * 16 + (lane & 7) + ((lane >> 3) & 1) * 8;
#pragma unroll
            for (int g = 0; g < 4; g++) {
                uint32_t voff = (uint32_t)(krow * APITCH + g * 16 + (lane >> 4) * 8) * 2;
                uint32_t Bh[4], Bl[4];
                LDSM4T(Bh, sbase + A_VH * 2 + voff);
                LDSM4T(Bl, sbase + A_VL * 2 + voff);
#pragma unroll
                for (int sub = 0; sub < 2; sub++)
                    MMA_BF16(O[g * 2 + sub], Aph, Bh[2 * sub], Bh[2 * sub + 1]);
#pragma unroll
                for (int sub = 0; sub < 2; sub++)
                    MMA_BF16(O[g * 2 + sub], Aph, Bl[2 * sub], Bl[2 * sub + 1]);
#pragma unroll
                for (int sub = 0; sub < 2; sub++)
                    MMA_BF16(O[g * 2 + sub], Apl, Bh[2 * sub], Bh[2 * sub + 1]);
            }
        }
    }

    // ---- write normalized output as fp16 hi/lo ----
    float i0 = 1.f / l0, i1 = 1.f / l1;
    size_t o0 = (size_t)q0 * DIM + h * HD;
    size_t o1 = (size_t)(q0 + 8) * DIM + h * HD;
#pragma unroll
    for (int j = 0; j < 8; j++) {
        int col = j * 8 + (lane & 3) * 2;
        uint32_t hi, lo;
        split2h(O[j][0] * i0, O[j][1] * i0, hi, lo);
        *(uint32_t*)(g_aoh + o0 + col) = hi;
        *(uint32_t*)(g_aol + o0 + col) = lo;
        split2h(O[j][2] * i1, O[j][3] * i1, hi, lo);
        *(uint32_t*)(g_aoh + o1 + col) = hi;
        *(uint32_t*)(g_aol + o1 + col) = lo;
    }
}

// ---------------- launch -----------------------------------------------------
extern "C" void kernel_launch(void* const* d_in, const int* in_sizes, int n_in,
                              void* d_out, int out_size)
{
    const float* x    = (const float*)d_in[0];
    const int*   pos  = (const int*)  d_in[1];
    const float* wqkv = (const float*)d_in[2];
    const float* wo   = (const float*)d_in[3];
    float*       out  = (float*)d_out;

    __nv_bfloat16 *pxh, *pxl, *pwqh, *pwql;
    __half *pwo16, *paoh, *paol;
    cudaGetSymbolAddress((void**)&pxh,   g_xh);
    cudaGetSymbolAddress((void**)&pxl,   g_xl);
    cudaGetSymbolAddress((void**)&pwqh,  g_wqh);
    cudaGetSymbolAddress((void**)&pwql,  g_wql);
    cudaGetSymbolAddress((void**)&pwo16, g_wo16);
    cudaGetSymbolAddress((void**)&paoh,  g_aoh);
    cudaGetSymbolAddress((void**)&paol,  g_aol);

    cudaFuncSetAttribute(gemm_qkv_kernel, cudaFuncAttributeMaxDynamicSharedMemorySize, GEMM_SMEM_QKV);
    cudaFuncSetAttribute(gemm_out_kernel, cudaFuncAttributeMaxDynamicSharedMemorySize, GEMM_SMEM_OUT);
    cudaFuncSetAttribute(attn_mma_kernel, cudaFuncAttributeMaxDynamicSharedMemorySize, ATTN_SMEM);

    // 0) fused preprocessing: splits + RoPE table, ONE launch
    preproc_kernel<<<(NPRE + 255) / 256, 256>>>(x, wqkv, wo, pos);

    // 1) QKV projection + fused table-RoPE/split -> q,k,v bf16 hi/lo directly
    gemm_qkv_kernel<<<dim3(QKVDIM / 128, SEQ / 128), 256, GEMM_SMEM_QKV>>>(
        pxh, pxl, pwqh, pwql, SEQ, QKVDIM, DIM);

    // 2) sliding-window attention (tensor cores), writes fp16 hi/lo ao
    attn_mma_kernel<<<dim3(SEQ / 128, NH), 256, ATTN_SMEM>>>();

    // 3) output projection (fp16 2-term, 4-stage, 3 CTAs/SM)
    gemm_out_kernel<<<dim3(DIM / 128, SEQ / 64), 256, GEMM_SMEM_OUT>>>(
        paoh, paol, pwo16, out, SEQ, DIM, DIM);
}